// round 5
// baseline (speedup 1.0000x reference)
#include <cuda_runtime.h>
#include <cstdint>

#define N_NODES 50000
#define N_EDGES 800000
#define D 256
#define D4 64

// ---------------- scratch (static __device__, no allocs) ----------------
__device__ int g_src[N_EDGES];
__device__ int g_dst[N_EDGES];
__device__ int g_csr[N_EDGES];
__device__ int g_deg[N_NODES];
__device__ int g_rowstart[N_NODES + 1];
__device__ int g_cursor[N_NODES];
__device__ float g_inv[N_NODES];
__device__ __align__(16) float g_mean[(size_t)N_NODES * D];
__device__ __align__(16) float g_h1[(size_t)N_NODES * D];
__device__ __align__(16) float g_h2[(size_t)N_NODES * D];
__device__ float g_logits[N_NODES];
__device__ unsigned g_maxbits;
__device__ float g_sum;
__device__ int g_nonzero;

// buffer selector so host never needs device-symbol addresses
__device__ __forceinline__ float* sel(int tag, const float* ext) {
    if (tag == 0) return (float*)ext;
    if (tag == 1) return g_mean;
    if (tag == 2) return g_h1;
    return g_h2;
}

// monotonic float<->uint for atomicMax
__device__ __forceinline__ unsigned fenc(float f) {
    unsigned u = __float_as_uint(f);
    return (u & 0x80000000u) ? ~u : (u | 0x80000000u);
}
__device__ __forceinline__ float fdec(unsigned u) {
    return (u & 0x80000000u) ? __uint_as_float(u ^ 0x80000000u)
                             : __uint_as_float(~u);
}

// ---------------- setup kernels ----------------
__global__ void k_init() {
    int i = blockIdx.x * blockDim.x + threadIdx.x;
    if (i < N_NODES) g_deg[i] = 0;
    if (i == 0) { g_nonzero = 0; g_maxbits = 0u; g_sum = 0.f; }
}

// int64 vs int32 edge_index detection: values < 50000, so in int64 (LE) every
// odd 32-bit word is 0. In int32 layout these words are random src indices.
__global__ void k_detect(const unsigned* __restrict__ ei) {
    unsigned v = ei[2 * threadIdx.x + 1];  // 1024 threads -> words 1..2047
    unsigned any = __ballot_sync(0xffffffffu, v != 0u);
    if ((threadIdx.x & 31) == 0 && any) atomicAdd(&g_nonzero, 1);
}

__global__ void k_decode(const void* __restrict__ ei) {
    int e = blockIdx.x * blockDim.x + threadIdx.x;
    if (e >= N_EDGES) return;
    int s, d;
    if (g_nonzero == 0) {
        const long long* p = (const long long*)ei;
        s = (int)p[e]; d = (int)p[N_EDGES + e];
    } else {
        const int* p = (const int*)ei;
        s = p[e]; d = p[N_EDGES + e];
    }
    g_src[e] = s; g_dst[e] = d;
    atomicAdd(&g_deg[d], 1);
}

__global__ void k_scan() {  // 1 block, 1024 threads: exclusive scan of g_deg
    __shared__ int warp_tot[32];
    __shared__ int carry_s;
    if (threadIdx.x == 0) carry_s = 0;
    __syncthreads();
    int lane = threadIdx.x & 31, w = threadIdx.x >> 5;
    for (int base = 0; base < N_NODES; base += 1024) {
        int i = base + threadIdx.x;
        int v = (i < N_NODES) ? g_deg[i] : 0;
        int incl = v;
        #pragma unroll
        for (int o = 1; o < 32; o <<= 1) {
            int t = __shfl_up_sync(0xffffffffu, incl, o);
            if (lane >= o) incl += t;
        }
        if (lane == 31) warp_tot[w] = incl;
        __syncthreads();
        if (w == 0) {
            int t = warp_tot[lane];
            int ti = t;
            #pragma unroll
            for (int o = 1; o < 32; o <<= 1) {
                int u = __shfl_up_sync(0xffffffffu, ti, o);
                if (lane >= o) ti += u;
            }
            warp_tot[lane] = ti - t;  // exclusive warp offsets
        }
        __syncthreads();
        int carry = carry_s;
        int excl = incl - v + warp_tot[w] + carry;
        if (i < N_NODES) {
            g_rowstart[i] = excl;
            g_cursor[i] = excl;
            g_inv[i] = v > 0 ? 1.0f / (float)v : 1.0f;
        }
        __syncthreads();
        if (threadIdx.x == 1023) carry_s = excl + v;
        __syncthreads();
    }
    if (threadIdx.x == 0) g_rowstart[N_NODES] = carry_s;
}

__global__ void k_fill() {
    int e = blockIdx.x * blockDim.x + threadIdx.x;
    if (e >= N_EDGES) return;
    int pos = atomicAdd(&g_cursor[g_dst[e]], 1);
    g_csr[pos] = g_src[e];
}

// ---------------- mean aggregation (block per node, 64 lanes x float4) ----
__global__ void k_agg(const float* __restrict__ ext, int srcTag) {
    const float4* X = (const float4*)sel(srcTag, ext);
    float4* OUT = (float4*)g_mean;
    int node = blockIdx.x;
    int s = g_rowstart[node], e = g_rowstart[node + 1];
    int t = threadIdx.x;
    float4 acc = make_float4(0.f, 0.f, 0.f, 0.f);
    __shared__ int nbr[64];
    for (int base = s; base < e; base += 64) {
        int cnt = min(64, e - base);
        __syncthreads();
        if (t < cnt) nbr[t] = g_csr[base + t];
        __syncthreads();
        int j = 0;
        for (; j + 4 <= cnt; j += 4) {
            int n0 = nbr[j], n1 = nbr[j + 1], n2 = nbr[j + 2], n3 = nbr[j + 3];
            float4 v0 = X[(size_t)n0 * D4 + t];
            float4 v1 = X[(size_t)n1 * D4 + t];
            float4 v2 = X[(size_t)n2 * D4 + t];
            float4 v3 = X[(size_t)n3 * D4 + t];
            acc.x += v0.x + v1.x + v2.x + v3.x;
            acc.y += v0.y + v1.y + v2.y + v3.y;
            acc.z += v0.z + v1.z + v2.z + v3.z;
            acc.w += v0.w + v1.w + v2.w + v3.w;
        }
        for (; j < cnt; j++) {
            float4 v = X[(size_t)nbr[j] * D4 + t];
            acc.x += v.x; acc.y += v.y; acc.z += v.z; acc.w += v.w;
        }
    }
    float inv = g_inv[node];
    OUT[(size_t)node * D4 + t] =
        make_float4(acc.x * inv, acc.y * inv, acc.z * inv, acc.w * inv);
}

// ---------------- fused SGEMM: C = mean@B0^T + A1@B1^T + bias (opt relu) ---
#define BM 128
#define BN 128
#define BK 16

__global__ void __launch_bounds__(256, 2) k_gemm(
    const float* __restrict__ ext, int a1Tag,
    const float* __restrict__ B0, const float* __restrict__ B1,
    const float* __restrict__ bias, int cTag, int relu)
{
    const float* A0 = g_mean;
    const float* A1 = sel(a1Tag, ext);
    float* C = sel(cTag, nullptr);

    __shared__ float As[BK][BM + 4];
    __shared__ float Bs[BK][BN + 4];

    const int tid = threadIdx.x;
    const int bm = blockIdx.y * BM, bn = blockIdx.x * BN;
    const int tx = tid & 15, ty = tid >> 4;
    const int lr = tid >> 2;         // 0..63
    const int lc = (tid & 3) << 2;   // 0,4,8,12

    float acc[8][8] = {};
    float4 rA[2], rB[2];

    auto gload = [&](int t) {
        int phase = t >> 4;
        int k0 = (t & 15) * BK;
        const float* A = phase ? A1 : A0;
        const float* B = phase ? B1 : B0;
        #pragma unroll
        for (int p = 0; p < 2; p++) {
            int row = lr + p * 64;
            int gm = bm + row;
            rA[p] = (gm < N_NODES)
                ? *(const float4*)(A + (size_t)gm * D + k0 + lc)
                : make_float4(0.f, 0.f, 0.f, 0.f);
            rB[p] = *(const float4*)(B + (size_t)(bn + row) * D + k0 + lc);
        }
    };
    auto sstore = [&]() {
        #pragma unroll
        for (int p = 0; p < 2; p++) {
            int row = lr + p * 64;
            As[lc + 0][row] = rA[p].x; As[lc + 1][row] = rA[p].y;
            As[lc + 2][row] = rA[p].z; As[lc + 3][row] = rA[p].w;
            Bs[lc + 0][row] = rB[p].x; Bs[lc + 1][row] = rB[p].y;
            Bs[lc + 2][row] = rB[p].z; Bs[lc + 3][row] = rB[p].w;
        }
    };

    gload(0); sstore();
    const int NT = 32;  // 2 phases x 16 K-tiles
    for (int t = 0; t < NT; t++) {
        __syncthreads();
        if (t + 1 < NT) gload(t + 1);
        #pragma unroll
        for (int kk = 0; kk < BK; kk++) {
            float a[8], b[8];
            *(float4*)&a[0] = *(const float4*)&As[kk][ty * 8];
            *(float4*)&a[4] = *(const float4*)&As[kk][ty * 8 + 4];
            *(float4*)&b[0] = *(const float4*)&Bs[kk][tx * 8];
            *(float4*)&b[4] = *(const float4*)&Bs[kk][tx * 8 + 4];
            #pragma unroll
            for (int i = 0; i < 8; i++)
                #pragma unroll
                for (int j = 0; j < 8; j++)
                    acc[i][j] += a[i] * b[j];
        }
        __syncthreads();
        if (t + 1 < NT) sstore();
    }

    float bs[8];
    #pragma unroll
    for (int j = 0; j < 8; j++) bs[j] = bias[bn + tx * 8 + j];
    #pragma unroll
    for (int i = 0; i < 8; i++) {
        int gm = bm + ty * 8 + i;
        if (gm < N_NODES) {
            float o[8];
            #pragma unroll
            for (int j = 0; j < 8; j++) {
                float v = acc[i][j] + bs[j];
                o[j] = relu ? fmaxf(v, 0.f) : v;
            }
            *(float4*)(C + (size_t)gm * D + bn + tx * 8)     = *(float4*)&o[0];
            *(float4*)(C + (size_t)gm * D + bn + tx * 8 + 4) = *(float4*)&o[4];
        }
    }
}

// ---------------- logits + softmax ----------------
__global__ void k_logits(const void* __restrict__ mention) {
    int m = (g_nonzero == 0) ? (int)((const long long*)mention)[0]
                             : ((const int*)mention)[0];
    int wg = (blockIdx.x * blockDim.x + threadIdx.x) >> 5;
    int lane = threadIdx.x & 31;
    if (wg >= N_NODES) return;
    const float4* H = (const float4*)g_h2;
    float s = 0.f;
    #pragma unroll
    for (int t = lane; t < D4; t += 32) {
        float4 a = H[(size_t)wg * D4 + t];
        float4 b = H[(size_t)m * D4 + t];
        s += a.x * b.x + a.y * b.y + a.z * b.z + a.w * b.w;
    }
    #pragma unroll
    for (int o = 16; o; o >>= 1) s += __shfl_down_sync(0xffffffffu, s, o);
    if (lane == 0) {
        g_logits[wg] = s;
        atomicMax(&g_maxbits, fenc(s));
    }
}

__global__ void k_exp(float* __restrict__ out) {
    int i = blockIdx.x * blockDim.x + threadIdx.x;
    float mx = fdec(g_maxbits);
    float v = 0.f;
    if (i < N_NODES) {
        v = expf(g_logits[i] - mx);
        out[i] = v;
    }
    #pragma unroll
    for (int o = 16; o; o >>= 1) v += __shfl_down_sync(0xffffffffu, v, o);
    __shared__ float wsum[8];
    int lane = threadIdx.x & 31, w = threadIdx.x >> 5;
    if (lane == 0) wsum[w] = v;
    __syncthreads();
    if (w == 0) {
        float s = (lane < 8) ? wsum[lane] : 0.f;
        #pragma unroll
        for (int o = 16; o; o >>= 1) s += __shfl_down_sync(0xffffffffu, s, o);
        if (lane == 0) atomicAdd(&g_sum, s);
    }
}

__global__ void k_norm(float* __restrict__ out) {
    int i = blockIdx.x * blockDim.x + threadIdx.x;
    if (i < N_NODES) out[i] *= (1.0f / g_sum);
}

// ---------------- launch ----------------
extern "C" void kernel_launch(void* const* d_in, const int* in_sizes, int n_in,
                              void* d_out, int out_size) {
    const float* x   = (const float*)d_in[0];
    const void*  ei  = d_in[1];
    const void*  men = d_in[2];
    const float* W1l = (const float*)d_in[3];
    const float* b1  = (const float*)d_in[4];
    const float* W1r = (const float*)d_in[5];
    const float* W2l = (const float*)d_in[6];
    const float* b2  = (const float*)d_in[7];
    const float* W2r = (const float*)d_in[8];
    float* out = (float*)d_out;

    const int EB = (N_EDGES + 255) / 256;   // 3125
    const int NB = (N_NODES + 255) / 256;   // 196

    k_init<<<NB, 256>>>();
    k_detect<<<1, 1024>>>((const unsigned*)ei);
    k_decode<<<EB, 256>>>(ei);
    k_scan<<<1, 1024>>>();
    k_fill<<<EB, 256>>>();

    dim3 gg(2, (N_NODES + BM - 1) / BM);    // (2, 391)

    // layer 1: mean(x) -> g_mean ; h1 = relu(mean@W1l^T + x@W1r^T + b1)
    k_agg<<<N_NODES, 64>>>(x, 0);
    k_gemm<<<gg, 256>>>(x, 0, W1l, W1r, b1, 2, 1);

    // layer 2: mean(h1) -> g_mean ; h2 = mean@W2l^T + h1@W2r^T + b2
    k_agg<<<N_NODES, 64>>>(nullptr, 2);
    k_gemm<<<gg, 256>>>(nullptr, 2, W2l, W2r, b2, 3, 0);

    // logits + softmax
    k_logits<<<(N_NODES * 32 + 255) / 256, 256>>>(men);
    k_exp<<<NB, 256>>>(out);
    k_norm<<<NB, 256>>>(out);
}

// round 7
// speedup vs baseline: 1.1752x; 1.1752x over previous
#include <cuda_runtime.h>
#include <cuda_bf16.h>
#include <cstdint>

#define N_NODES 50000
#define N_EDGES 800000
#define D 256
#define D4 64

// ---------------- scratch (static __device__, no allocs) ----------------
__device__ int g_src[N_EDGES];
__device__ int g_dst[N_EDGES];
__device__ int g_csr[N_EDGES];
__device__ int g_deg[N_NODES];
__device__ int g_rowstart[N_NODES + 1];
__device__ int g_cursor[N_NODES];
__device__ float g_inv[N_NODES];
__device__ float g_logits[N_NODES];
__device__ unsigned g_maxbits;
__device__ float g_sum;
__device__ int g_nonzero;

// bf16 hi/lo split arrays
__device__ __align__(16) __nv_bfloat16 g_xh[(size_t)N_NODES * D];
__device__ __align__(16) __nv_bfloat16 g_xl[(size_t)N_NODES * D];
__device__ __align__(16) __nv_bfloat16 g_mh[(size_t)N_NODES * D];
__device__ __align__(16) __nv_bfloat16 g_ml[(size_t)N_NODES * D];
__device__ __align__(16) __nv_bfloat16 g_h1h[(size_t)N_NODES * D];
__device__ __align__(16) __nv_bfloat16 g_h1l[(size_t)N_NODES * D];
__device__ __align__(16) float g_h2[(size_t)N_NODES * D];
__device__ __align__(16) __nv_bfloat16 g_wh[4 * D * D];   // W1l,W1r,W2l,W2r
__device__ __align__(16) __nv_bfloat16 g_wl[4 * D * D];

// ---------------- helpers ----------------
__device__ __forceinline__ uint32_t smem_u32(const void* p) {
    uint32_t a;
    asm("{ .reg .u64 t; cvta.to.shared.u64 t, %1; cvt.u32.u64 %0, t; }"
        : "=r"(a) : "l"(p));
    return a;
}
__device__ __forceinline__ void cp16(uint32_t saddr, const void* g, bool pred) {
    int sz = pred ? 16 : 0;
    asm volatile("cp.async.cg.shared.global [%0], [%1], 16, %2;"
                 :: "r"(saddr), "l"(g), "r"(sz) : "memory");
}
#define CP_COMMIT() asm volatile("cp.async.commit_group;" ::: "memory")
#define CP_WAIT1()  asm volatile("cp.async.wait_group 1;" ::: "memory")
#define CP_WAIT0()  asm volatile("cp.async.wait_group 0;" ::: "memory")

__device__ __forceinline__ void ldm_x4(uint32_t* r, uint32_t addr) {
    asm volatile("ldmatrix.sync.aligned.m8n8.x4.shared.b16 {%0,%1,%2,%3}, [%4];"
                 : "=r"(r[0]), "=r"(r[1]), "=r"(r[2]), "=r"(r[3]) : "r"(addr));
}
__device__ __forceinline__ void mma16816(float* c, const uint32_t* a,
                                         uint32_t b0, uint32_t b1) {
    asm volatile(
        "mma.sync.aligned.m16n8k16.row.col.f32.bf16.bf16.f32 "
        "{%0,%1,%2,%3}, {%4,%5,%6,%7}, {%8,%9}, {%0,%1,%2,%3};"
        : "+f"(c[0]), "+f"(c[1]), "+f"(c[2]), "+f"(c[3])
        : "r"(a[0]), "r"(a[1]), "r"(a[2]), "r"(a[3]), "r"(b0), "r"(b1));
}

// monotonic float<->uint for atomicMax
__device__ __forceinline__ unsigned fenc(float f) {
    unsigned u = __float_as_uint(f);
    return (u & 0x80000000u) ? ~u : (u | 0x80000000u);
}
__device__ __forceinline__ float fdec(unsigned u) {
    return (u & 0x80000000u) ? __uint_as_float(u ^ 0x80000000u)
                             : __uint_as_float(~u);
}
// hi/lo bf16 split helpers
__device__ __forceinline__ uint32_t packhi2(float a, float b, float* ra, float* rb) {
    __nv_bfloat16 ha = __float2bfloat16(a), hb = __float2bfloat16(b);
    *ra = a - __bfloat162float(ha);
    *rb = b - __bfloat162float(hb);
    __nv_bfloat162 p; p.x = ha; p.y = hb;
    return *(uint32_t*)&p;
}
__device__ __forceinline__ uint32_t packlo2(float a, float b) {
    __nv_bfloat162 p; p.x = __float2bfloat16(a); p.y = __float2bfloat16(b);
    return *(uint32_t*)&p;
}

// ---------------- setup kernels ----------------
__global__ void k_init() {
    int i = blockIdx.x * blockDim.x + threadIdx.x;
    if (i < N_NODES) g_deg[i] = 0;
    if (i == 0) { g_nonzero = 0; g_maxbits = 0u; g_sum = 0.f; }
}

__global__ void k_detect(const unsigned* __restrict__ ei) {
    unsigned v = ei[2 * threadIdx.x + 1];
    unsigned any = __ballot_sync(0xffffffffu, v != 0u);
    if ((threadIdx.x & 31) == 0 && any) atomicAdd(&g_nonzero, 1);
}

__global__ void k_decode(const void* __restrict__ ei) {
    int e = blockIdx.x * blockDim.x + threadIdx.x;
    if (e >= N_EDGES) return;
    int s, d;
    if (g_nonzero == 0) {
        const long long* p = (const long long*)ei;
        s = (int)p[e]; d = (int)p[N_EDGES + e];
    } else {
        const int* p = (const int*)ei;
        s = p[e]; d = p[N_EDGES + e];
    }
    g_src[e] = s; g_dst[e] = d;
    atomicAdd(&g_deg[d], 1);
}

// fast scan: 1 block, 1024 threads, 49 contiguous elems/thread, 2 barriers
__global__ void k_scan() {
    const int PER = 49;  // 1024*49 = 50176 >= N_NODES
    int t = threadIdx.x, lane = t & 31, w = t >> 5;
    int start = t * PER;
    int sum = 0;
    for (int i = 0; i < PER; i++) {
        int idx = start + i;
        sum += (idx < N_NODES) ? g_deg[idx] : 0;
    }
    int incl = sum;
    #pragma unroll
    for (int o = 1; o < 32; o <<= 1) {
        int v = __shfl_up_sync(0xffffffffu, incl, o);
        if (lane >= o) incl += v;
    }
    __shared__ int wt[32];
    if (lane == 31) wt[w] = incl;
    __syncthreads();
    if (w == 0) {
        int v = wt[lane], iv = v;
        #pragma unroll
        for (int o = 1; o < 32; o <<= 1) {
            int u = __shfl_up_sync(0xffffffffu, iv, o);
            if (lane >= o) iv += u;
        }
        wt[lane] = iv - v;
    }
    __syncthreads();
    int run = (incl - sum) + wt[w];
    for (int i = 0; i < PER; i++) {
        int idx = start + i;
        if (idx < N_NODES) {
            int v = g_deg[idx];
            g_rowstart[idx] = run; g_cursor[idx] = run;
            g_inv[idx] = v > 0 ? 1.0f / (float)v : 1.0f;
            run += v;
        }
    }
    if (t == 0) g_rowstart[N_NODES] = N_EDGES;
}

__global__ void k_fill() {
    int e = blockIdx.x * blockDim.x + threadIdx.x;
    if (e >= N_EDGES) return;
    int pos = atomicAdd(&g_cursor[g_dst[e]], 1);
    g_csr[pos] = g_src[e];
}

// ---------------- bf16 split conversion ----------------
__global__ void k_convx(const float* __restrict__ x) {
    size_t i = (size_t)blockIdx.x * blockDim.x + threadIdx.x;  // per 4 elems
    if (i >= (size_t)N_NODES * D4) return;
    float4 v = ((const float4*)x)[i];
    float r0, r1, r2, r3;
    uint32_t h01 = packhi2(v.x, v.y, &r0, &r1);
    uint32_t h23 = packhi2(v.z, v.w, &r2, &r3);
    ((uint2*)g_xh)[i] = make_uint2(h01, h23);
    ((uint2*)g_xl)[i] = make_uint2(packlo2(r0, r1), packlo2(r2, r3));
}

__global__ void k_convw(const float* __restrict__ w1l, const float* __restrict__ w1r,
                        const float* __restrict__ w2l, const float* __restrict__ w2r) {
    int i = blockIdx.x * blockDim.x + threadIdx.x;  // per 4 elems, 65536 total
    if (i >= 4 * D * D / 4) return;
    int mat = i >> 14, off = i & 16383;
    const float* src = mat == 0 ? w1l : mat == 1 ? w1r : mat == 2 ? w2l : w2r;
    float4 v = ((const float4*)src)[off];
    float r0, r1, r2, r3;
    uint32_t h01 = packhi2(v.x, v.y, &r0, &r1);
    uint32_t h23 = packhi2(v.z, v.w, &r2, &r3);
    size_t o = (size_t)mat * (D * D / 4) + off;
    ((uint2*)g_wh)[o] = make_uint2(h01, h23);
    ((uint2*)g_wl)[o] = make_uint2(packlo2(r0, r1), packlo2(r2, r3));
}

// ---------------- mean aggregation -> bf16 hi/lo ----------------
__device__ __forceinline__ float4 rowval(const float4* X, int mode, int n, int t) {
    if (mode == 0) return X[(size_t)n * D4 + t];
    uint2 a = ((const uint2*)g_h1h)[(size_t)n * D4 + t];
    uint2 b = ((const uint2*)g_h1l)[(size_t)n * D4 + t];
    float2 f0 = __bfloat1622float2(*(__nv_bfloat162*)&a.x);
    float2 f1 = __bfloat1622float2(*(__nv_bfloat162*)&a.y);
    float2 e0 = __bfloat1622float2(*(__nv_bfloat162*)&b.x);
    float2 e1 = __bfloat1622float2(*(__nv_bfloat162*)&b.y);
    return make_float4(f0.x + e0.x, f0.y + e0.y, f1.x + e1.x, f1.y + e1.y);
}

__global__ void k_agg(const float* __restrict__ ext, int mode) {
    const float4* X = (const float4*)ext;
    int node = blockIdx.x;
    int s = g_rowstart[node], e = g_rowstart[node + 1];
    int t = threadIdx.x;
    float4 acc = make_float4(0.f, 0.f, 0.f, 0.f);
    __shared__ int nbr[64];
    for (int base = s; base < e; base += 64) {
        int cnt = min(64, e - base);
        __syncthreads();
        if (t < cnt) nbr[t] = g_csr[base + t];
        __syncthreads();
        int j = 0;
        for (; j + 4 <= cnt; j += 4) {
            float4 v0 = rowval(X, mode, nbr[j], t);
            float4 v1 = rowval(X, mode, nbr[j + 1], t);
            float4 v2 = rowval(X, mode, nbr[j + 2], t);
            float4 v3 = rowval(X, mode, nbr[j + 3], t);
            acc.x += v0.x + v1.x + v2.x + v3.x;
            acc.y += v0.y + v1.y + v2.y + v3.y;
            acc.z += v0.z + v1.z + v2.z + v3.z;
            acc.w += v0.w + v1.w + v2.w + v3.w;
        }
        for (; j < cnt; j++) {
            float4 v = rowval(X, mode, nbr[j], t);
            acc.x += v.x; acc.y += v.y; acc.z += v.z; acc.w += v.w;
        }
    }
    float inv = g_inv[node];
    float m0 = acc.x * inv, m1 = acc.y * inv, m2 = acc.z * inv, m3 = acc.w * inv;
    float r0, r1, r2, r3;
    uint32_t h01 = packhi2(m0, m1, &r0, &r1);
    uint32_t h23 = packhi2(m2, m3, &r2, &r3);
    size_t idx = (size_t)node * D4 + t;
    ((uint2*)g_mh)[idx] = make_uint2(h01, h23);
    ((uint2*)g_ml)[idx] = make_uint2(packlo2(r0, r1), packlo2(r2, r3));
}

// ---------------- mma.sync bf16 GEMM ----------------
// Block tile: 64 (M) x 256 (N), BK=32, 8 warps (2x4), warp tile 32x64.
// C = mean@B0^T + A1@B1^T + bias, 3-term hi/lo split each -> 6 term-GEMMs
// sharing one fp32 accumulator. SMEM rows padded to 80B (conflict-free
// ldmatrix), cp.async double-buffered.
#define RS 80                         // bytes per smem row (32 bf16 + pad)
#define A_OFF(buf) ((buf) * 64 * RS)                 // 2 x 5120
#define B_OFF(buf) (10240 + (buf) * 256 * RS)        // 2 x 20480
#define SMEM_SZ 51200

__global__ void __launch_bounds__(256, 1) k_mma(int layer, const float* __restrict__ bias) {
    extern __shared__ char smem[];
    uint32_t sb = smem_u32(smem);
    const int tid = threadIdx.x, lane = tid & 31, wid = tid >> 5;
    const int warpM = wid >> 2, warpN = wid & 3;
    const int bm = blockIdx.x * 64;

    const __nv_bfloat16* Ap[4];
    Ap[0] = g_mh; Ap[1] = g_ml;
    Ap[2] = layer ? g_h1h : g_xh;
    Ap[3] = layer ? g_h1l : g_xl;
    const __nv_bfloat16* Bp[4];
    int w0 = layer ? 2 : 0, w1 = layer ? 3 : 1;
    Bp[0] = g_wh + (size_t)w0 * D * D; Bp[1] = g_wl + (size_t)w0 * D * D;
    Bp[2] = g_wh + (size_t)w1 * D * D; Bp[3] = g_wl + (size_t)w1 * D * D;
    const int asel[6] = {0, 0, 1, 2, 2, 3};
    const int bsel[6] = {0, 1, 0, 2, 3, 2};

    // per-thread fill coordinates
    const int frow = tid >> 2, fc16 = tid & 3;
    const int fgm = bm + frow;
    const bool fok = fgm < N_NODES;

    auto fill = [&](int it) {
        int t = it >> 3, kc = it & 7, buf = it & 1;
        const __nv_bfloat16* Aarr = Ap[asel[t]];
        const __nv_bfloat16* Barr = Bp[bsel[t]];
        cp16(sb + A_OFF(buf) + frow * RS + fc16 * 16,
             Aarr + (size_t)fgm * D + kc * 32 + fc16 * 8, fok);
        #pragma unroll
        for (int i2 = 0; i2 < 4; i2++) {
            int br = frow + i2 * 64;
            cp16(sb + B_OFF(buf) + br * RS + fc16 * 16,
                 Barr + (size_t)br * D + kc * 32 + fc16 * 8, true);
        }
        CP_COMMIT();
    };

    float c[2][8][4];
    #pragma unroll
    for (int i = 0; i < 2; i++)
        #pragma unroll
        for (int j = 0; j < 8; j++)
            #pragma unroll
            for (int q = 0; q < 4; q++) c[i][j][q] = 0.f;

    const int lr = lane & 7, grp = lane >> 3;
    const int NT = 48;  // 6 terms x 8 K-chunks

    fill(0);
    for (int it = 0; it < NT; it++) {
        if (it + 1 < NT) { fill(it + 1); CP_WAIT1(); }
        else             { CP_WAIT0(); }
        __syncthreads();
        int buf = it & 1;
        uint32_t abase = sb + A_OFF(buf);
        uint32_t bbase = sb + B_OFF(buf);
        #pragma unroll
        for (int ks = 0; ks < 2; ks++) {
            uint32_t a[2][4], b[4][4];
            #pragma unroll
            for (int mt = 0; mt < 2; mt++) {
                int m = warpM * 32 + mt * 16 + (grp & 1) * 8 + lr;
                ldm_x4(a[mt], abase + m * RS + ks * 32 + (grp >> 1) * 16);
            }
            #pragma unroll
            for (int bt = 0; bt < 4; bt++) {
                int n = warpN * 64 + bt * 16 + (grp >> 1) * 8 + lr;
                ldm_x4(b[bt], bbase + n * RS + ks * 32 + (grp & 1) * 16);
            }
            #pragma unroll
            for (int mt = 0; mt < 2; mt++)
                #pragma unroll
                for (int nt = 0; nt < 8; nt++)
                    mma16816(c[mt][nt], a[mt], b[nt >> 1][(nt & 1) * 2],
                             b[nt >> 1][(nt & 1) * 2 + 1]);
        }
        __syncthreads();
    }

    // epilogue
    #pragma unroll
    for (int nt = 0; nt < 8; nt++) {
        int n = warpN * 64 + nt * 8 + (lane & 3) * 2;
        float b0 = bias[n], b1 = bias[n + 1];
        #pragma unroll
        for (int mt = 0; mt < 2; mt++) {
            #pragma unroll
            for (int half = 0; half < 2; half++) {
                int row = bm + warpM * 32 + mt * 16 + (lane >> 2) + half * 8;
                if (row >= N_NODES) continue;
                float v0 = c[mt][nt][half * 2]     + b0;
                float v1 = c[mt][nt][half * 2 + 1] + b1;
                if (layer == 0) {
                    v0 = fmaxf(v0, 0.f); v1 = fmaxf(v1, 0.f);
                    float r0, r1;
                    uint32_t h = packhi2(v0, v1, &r0, &r1);
                    uint32_t l = packlo2(r0, r1);
                    size_t o = (size_t)row * D + n;
                    *(uint32_t*)&g_h1h[o] = h;
                    *(uint32_t*)&g_h1l[o] = l;
                } else {
                    *(float2*)&g_h2[(size_t)row * D + n] = make_float2(v0, v1);
                }
            }
        }
    }
}

// ---------------- logits + softmax ----------------
__global__ void k_logits(const void* __restrict__ mention) {
    int m = (g_nonzero == 0) ? (int)((const long long*)mention)[0]
                             : ((const int*)mention)[0];
    int wg = (blockIdx.x * blockDim.x + threadIdx.x) >> 5;
    int lane = threadIdx.x & 31;
    if (wg >= N_NODES) return;
    const float4* H = (const float4*)g_h2;
    float s = 0.f;
    #pragma unroll
    for (int t = lane; t < D4; t += 32) {
        float4 a = H[(size_t)wg * D4 + t];
        float4 b = H[(size_t)m * D4 + t];
        s += a.x * b.x + a.y * b.y + a.z * b.z + a.w * b.w;
    }
    #pragma unroll
    for (int o = 16; o; o >>= 1) s += __shfl_down_sync(0xffffffffu, s, o);
    if (lane == 0) {
        g_logits[wg] = s;
        atomicMax(&g_maxbits, fenc(s));
    }
}

__global__ void k_exp(float* __restrict__ out) {
    int i = blockIdx.x * blockDim.x + threadIdx.x;
    float mx = fdec(g_maxbits);
    float v = 0.f;
    if (i < N_NODES) {
        v = expf(g_logits[i] - mx);
        out[i] = v;
    }
    #pragma unroll
    for (int o = 16; o; o >>= 1) v += __shfl_down_sync(0xffffffffu, v, o);
    __shared__ float wsum[8];
    int lane = threadIdx.x & 31, w = threadIdx.x >> 5;
    if (lane == 0) wsum[w] = v;
    __syncthreads();
    if (w == 0) {
        float s = (lane < 8) ? wsum[lane] : 0.f;
        #pragma unroll
        for (int o = 16; o; o >>= 1) s += __shfl_down_sync(0xffffffffu, s, o);
        if (lane == 0) atomicAdd(&g_sum, s);
    }
}

__global__ void k_norm(float* __restrict__ out) {
    int i = blockIdx.x * blockDim.x + threadIdx.x;
    if (i < N_NODES) out[i] *= (1.0f / g_sum);
}

// ---------------- launch ----------------
extern "C" void kernel_launch(void* const* d_in, const int* in_sizes, int n_in,
                              void* d_out, int out_size) {
    const float* x   = (const float*)d_in[0];
    const void*  ei  = d_in[1];
    const void*  men = d_in[2];
    const float* W1l = (const float*)d_in[3];
    const float* b1  = (const float*)d_in[4];
    const float* W1r = (const float*)d_in[5];
    const float* W2l = (const float*)d_in[6];
    const float* b2  = (const float*)d_in[7];
    const float* W2r = (const float*)d_in[8];
    float* out = (float*)d_out;

    const int EB = (N_EDGES + 255) / 256;
    const int NB = (N_NODES + 255) / 256;
    const int GT = (N_NODES + 63) / 64;     // 782 GEMM tiles

    static bool attr_done = false;
    if (!attr_done) {
        cudaFuncSetAttribute(k_mma, cudaFuncAttributeMaxDynamicSharedMemorySize, SMEM_SZ);
        attr_done = true;
    }

    k_init<<<NB, 256>>>();
    k_detect<<<1, 1024>>>((const unsigned*)ei);
    k_decode<<<EB, 256>>>(ei);
    k_scan<<<1, 1024>>>();
    k_fill<<<EB, 256>>>();

    k_convx<<<(N_NODES * D4 + 255) / 256, 256>>>(x);
    k_convw<<<(4 * D * D / 4 + 255) / 256, 256>>>(W1l, W1r, W2l, W2r);

    // layer 1: mean(x) -> hi/lo ; h1 = relu(mean@W1l^T + x@W1r^T + b1) -> hi/lo
    k_agg<<<N_NODES, 64>>>(x, 0);
    k_mma<<<GT, 256, SMEM_SZ>>>(0, b1);

    // layer 2: mean(h1) -> hi/lo ; h2 = mean@W2l^T + h1@W2r^T + b2 (fp32)
    k_agg<<<N_NODES, 64>>>(nullptr, 1);
    k_mma<<<GT, 256, SMEM_SZ>>>(1, b2);

    k_logits<<<(N_NODES * 32 + 255) / 256, 256>>>(men);
    k_exp<<<NB, 256>>>(out);
    k_norm<<<NB, 256>>>(out);
}